// round 15
// baseline (speedup 1.0000x reference)
#include <cuda_runtime.h>
#include <math.h>
#include <stdint.h>

#define H       16
#define DM      1024
#define DK      64
#define NW      16384
#define NCHUNK  256     // attn blocks; 64 rows each

typedef unsigned long long u64;

// ---- scratch (static __device__ arrays; no allocation) ----
__device__ __align__(16) float g_q[DM];
__device__ __align__(16) float g_a[H * DM];
__device__ __align__(16) float g_c[H];
__device__ __align__(16) float g_Zpart[H * 512];
__device__ __align__(16) float g_wpart[NCHUNK][H * DM];
__device__ __align__(16) float g_w[H * DM];
__device__ __align__(16) float g_x[DM];

__device__ __forceinline__ float warp_red(float v) {
#pragma unroll
    for (int o = 16; o; o >>= 1) v += __shfl_down_sync(0xffffffffu, v, o);
    return v;
}

// packed f32x2 FMA (Blackwell)
__device__ __forceinline__ u64 fma2(u64 a, u64 b, u64 c) {
    u64 d;
    asm("fma.rn.f32x2 %0, %1, %2, %3;" : "=l"(d) : "l"(a), "l"(b), "l"(c));
    return d;
}
__device__ __forceinline__ float sum2(u64 v) {
    return __uint_as_float((unsigned)v) + __uint_as_float((unsigned)(v >> 32));
}

// cp.async helpers
__device__ __forceinline__ void cp_async16(uint32_t smem_addr, const void* gptr) {
    asm volatile("cp.async.cg.shared.global [%0], [%1], 16;"
                 :: "r"(smem_addr), "l"(gptr));
}
#define CP_COMMIT()  asm volatile("cp.async.commit_group;")
#define CP_WAIT(n)   asm volatile("cp.async.wait_group %0;" :: "n"(n))

// k_attn dynamic SMEM layout (floats) — round-6 champion layout:
#define SM_A    0
#define SM_KT0  16384
#define SM_KT1  (16384 + 4224)
#define SM_P2   (16384 + 8448)
#define SM_BYTES ((16384 + 8448) * 4 + 1024 * 8)   // 107520

// ------------------------------------------------------------------
// 1) q[i] = dot(query, Wq[i]) + bq[i].  grid 128 x 256 (r6 verbatim)
// ------------------------------------------------------------------
__global__ void k_qproj(const float* __restrict__ query,
                        const float* __restrict__ Wq,
                        const float* __restrict__ bq) {
    __shared__ __align__(16) float qs[DM];
    const int tid = threadIdx.x;
    for (int i = tid; i < DM; i += 256) qs[i] = query[i];
    __syncthreads();
    const int w = tid >> 5, lane = tid & 31;
    const int row = blockIdx.x * 8 + w;
    const float4* wr = (const float4*)(Wq + (size_t)row * DM);
    const float4* q4 = (const float4*)qs;
    float acc = 0.f;
#pragma unroll 8
    for (int k = lane; k < DM / 4; k += 32) {
        float4 a = wr[k], b = q4[k];
        acc += a.x * b.x + a.y * b.y + a.z * b.z + a.w * b.w;
    }
    acc = warp_red(acc);
    if (lane == 0) g_q[row] = acc + bq[row];
}

// ------------------------------------------------------------------
// 2) a[h][j] = sum_d q[h*64+d]*Wk[h*64+d][j];  c[h] (r6 verbatim)
// ------------------------------------------------------------------
__global__ void k_aprep(const float* __restrict__ Wk,
                        const float* __restrict__ bk) {
    const int h = blockIdx.x >> 3, sl = blockIdx.x & 7;
    const int tid = threadIdx.x;
    __shared__ float qh[DK];
    if (tid < DK) qh[tid] = g_q[h * DK + tid];
    __syncthreads();
    const int j = sl * 128 + tid;
    const float* base = Wk + (size_t)(h * DK) * DM + j;
    float acc = 0.f;
#pragma unroll 8
    for (int d = 0; d < DK; d++) acc += qh[d] * base[(size_t)d * DM];
    g_a[h * DM + j] = acc;
    if (sl == 0 && tid < 32) {
        float c = 0.f;
        for (int d = tid; d < DK; d += 32) c += qh[d] * bk[h * DK + d];
        c = warp_red(c);
        if (tid == 0) g_c[h] = c;
    }
}

// ------------------------------------------------------------------
// 3) FUSED attention — round-6 champion, verbatim.
// ------------------------------------------------------------------
__global__ void __launch_bounds__(256, 2) k_attn(const float* __restrict__ key,
                                                 const float* __restrict__ value) {
    extern __shared__ __align__(16) float smem[];
    float* a_s = smem + SM_A;
    u64*   p2  = (u64*)(smem + SM_P2);

    const int tid = threadIdx.x;
    const int w = tid >> 5, lane = tid & 31;
    const int n0 = blockIdx.x * 64;

    const uint32_t smem_u32 = (uint32_t)__cvta_generic_to_shared(smem);
    const uint32_t a_addr   = smem_u32 + SM_A * 4;
    const uint32_t kt_addr[2] = { smem_u32 + SM_KT0 * 4, smem_u32 + SM_KT1 * 4 };

    const int r_ld = tid >> 3;   // key stage: row (0..31)
    const int c4b  = tid & 7;    // key stage: f4 col base

    // ---- prologue: a (once) ----
#pragma unroll
    for (int k = 0; k < 16; k++) {
        const int f4 = tid + 256 * k;
        cp_async16(a_addr + f4 * 16, (const float4*)g_a + f4);
    }
    CP_COMMIT();

    // ---------------- Phase A ----------------
#pragma unroll 1
    for (int sub = 0; sub < 2; sub++) {
        const int n0s = n0 + sub * 32;
        const float* krow = key + (size_t)(n0s + r_ld) * DM;

#pragma unroll
        for (int k = 0; k < 4; k++) {
            const int c4 = c4b + 8 * k;
            cp_async16(kt_addr[0] + (r_ld * 132 + c4 * 4) * 4, krow + c4 * 4);
        }
        CP_COMMIT();
#pragma unroll
        for (int k = 0; k < 4; k++) {
            const int c4 = c4b + 8 * k;
            cp_async16(kt_addr[1] + (r_ld * 132 + c4 * 4) * 4, krow + 128 + c4 * 4);
        }
        CP_COMMIT();

        ulonglong2 acc2[16];
#pragma unroll
        for (int h = 0; h < 16; h++) acc2[h] = make_ulonglong2(0ull, 0ull);

#pragma unroll
        for (int t = 0; t < 8; t++) {
            if (t == 7) { CP_WAIT(0); } else { CP_WAIT(1); }
            __syncthreads();
            const float* ktb = smem + ((t & 1) ? SM_KT1 : SM_KT0);
#pragma unroll
            for (int q = 0; q < 4; q++) {
                const int j = w * 16 + q * 4;
                const ulonglong2 kv = *(const ulonglong2*)&ktb[lane * 132 + j];
#pragma unroll
                for (int h = 0; h < 16; h++) {
                    const ulonglong2 av = *(const ulonglong2*)&a_s[h * 1024 + t * 128 + j];
                    acc2[h].x = fma2(kv.x, av.x, acc2[h].x);
                    acc2[h].y = fma2(kv.y, av.y, acc2[h].y);
                }
            }
            __syncthreads();
            if (t < 6) {
                const uint32_t dst = kt_addr[t & 1];
#pragma unroll
                for (int k = 0; k < 4; k++) {
                    const int c4 = c4b + 8 * k;
                    cp_async16(dst + (r_ld * 132 + c4 * 4) * 4,
                               krow + (t + 2) * 128 + c4 * 4);
                }
                CP_COMMIT();
            }
        }

        float* red = smem + SM_KT0;
#pragma unroll
        for (int h = 0; h < 16; h++)
            red[h * 256 + w * 32 + lane] = sum2(acc2[h].x) + sum2(acc2[h].y);
        __syncthreads();
        const int h0 = tid >> 5;
        const int r  = tid & 31;
#pragma unroll
        for (int s = 0; s < 2; s++) {
            const int hh = h0 + 8 * s;
            float v = g_c[hh];
#pragma unroll
            for (int ww = 0; ww < 8; ww++) v += red[hh * 256 + ww * 32 + r];
            const float e = __expf(v);
            const unsigned b = __float_as_uint(e);
            p2[hh * 64 + sub * 32 + r] = ((u64)b << 32) | b;
            float z = warp_red(e);
            if (r == 0) g_Zpart[hh * 512 + blockIdx.x * 2 + sub] = z;
        }
        __syncthreads();
    }

    // ---------------- Phase B ----------------
    ulonglong2 acc[H];
#pragma unroll
    for (int h = 0; h < H; h++) acc[h] = make_ulonglong2(0ull, 0ull);

    const ulonglong2* vp = (const ulonglong2*)value + (size_t)n0 * 256 + tid;

    for (int nb = 0; nb < 64; nb += 8) {
        ulonglong2 v0 = vp[(size_t)(nb + 0) * 256];
        ulonglong2 v1 = vp[(size_t)(nb + 1) * 256];
        ulonglong2 v2 = vp[(size_t)(nb + 2) * 256];
        ulonglong2 v3 = vp[(size_t)(nb + 3) * 256];
        ulonglong2 v4 = vp[(size_t)(nb + 4) * 256];
        ulonglong2 v5 = vp[(size_t)(nb + 5) * 256];
        ulonglong2 v6 = vp[(size_t)(nb + 6) * 256];
        ulonglong2 v7 = vp[(size_t)(nb + 7) * 256];
#pragma unroll
        for (int h = 0; h < H; h++) {
            const u64* ph = &p2[h * 64 + nb];
            const ulonglong2 pA = *(const ulonglong2*)(ph + 0);
            const ulonglong2 pB = *(const ulonglong2*)(ph + 2);
            const ulonglong2 pC = *(const ulonglong2*)(ph + 4);
            const ulonglong2 pD = *(const ulonglong2*)(ph + 6);
            acc[h].x = fma2(pA.x, v0.x, acc[h].x); acc[h].y = fma2(pA.x, v0.y, acc[h].y);
            acc[h].x = fma2(pA.y, v1.x, acc[h].x); acc[h].y = fma2(pA.y, v1.y, acc[h].y);
            acc[h].x = fma2(pB.x, v2.x, acc[h].x); acc[h].y = fma2(pB.x, v2.y, acc[h].y);
            acc[h].x = fma2(pB.y, v3.x, acc[h].x); acc[h].y = fma2(pB.y, v3.y, acc[h].y);
            acc[h].x = fma2(pC.x, v4.x, acc[h].x); acc[h].y = fma2(pC.x, v4.y, acc[h].y);
            acc[h].x = fma2(pC.y, v5.x, acc[h].x); acc[h].y = fma2(pC.y, v5.y, acc[h].y);
            acc[h].x = fma2(pD.x, v6.x, acc[h].x); acc[h].y = fma2(pD.x, v6.y, acc[h].y);
            acc[h].x = fma2(pD.y, v7.x, acc[h].x); acc[h].y = fma2(pD.y, v7.y, acc[h].y);
        }
    }
    ulonglong2* wp = (ulonglong2*)&g_wpart[blockIdx.x][0];
#pragma unroll
    for (int h = 0; h < H; h++) wp[h * 256 + tid] = acc[h];
}

// ------------------------------------------------------------------
// 4) w[i] = (sum_c wpart[c][i]) / Z[h].  grid 1024 x 256.
//    Thread = (f4col in 4, cseg in 64) x 4 chunks -> 55 warps/SM.
// ------------------------------------------------------------------
__global__ void k_wreduce() {
    __shared__ __align__(16) float4 part[256];
    __shared__ float zs;
    const int tid = threadIdx.x;
    const int fl   = tid & 3;                 // f4 col within block
    const int cseg = tid >> 2;                // 0..63 (4 chunks each)
    const int b = blockIdx.x;
    const int h = b >> 6;                     // 64 blocks per head
    const int f4col = b * 4 + fl;

    const float4* wp4 = (const float4*)&g_wpart[0][0];
    float4 acc = make_float4(0.f, 0.f, 0.f, 0.f);
#pragma unroll
    for (int k = 0; k < 4; k++) {
        const float4 v = wp4[(size_t)(cseg * 4 + k) * 4096 + f4col];
        acc.x += v.x; acc.y += v.y; acc.z += v.z; acc.w += v.w;
    }
    part[tid] = acc;

    if (tid < 32) {
        const float4* zp = (const float4*)(g_Zpart + h * 512);
        float z = 0.f;
#pragma unroll
        for (int k = 0; k < 4; k++) {
            const float4 v = zp[tid * 4 + k];
            z += v.x + v.y + v.z + v.w;
        }
        z = warp_red(z);
        if (tid == 0) zs = z;
    }
    __syncthreads();

    // tree-combine 64 csegs -> 4 cols (fixed order)
    if (tid < 128) {
        float4 a = part[tid], bx = part[tid + 128];
        a.x += bx.x; a.y += bx.y; a.z += bx.z; a.w += bx.w;
        part[tid] = a;
    }
    __syncthreads();
    if (tid < 64) {
        float4 a = part[tid], bx = part[tid + 64];
        a.x += bx.x; a.y += bx.y; a.z += bx.z; a.w += bx.w;
        part[tid] = a;
    }
    __syncthreads();
    if (tid < 4) {
        float4 s = part[tid];
#pragma unroll
        for (int g = 1; g < 16; g++) {
            const float4 v = part[g * 4 + tid];
            s.x += v.x; s.y += v.y; s.z += v.z; s.w += v.w;
        }
        const float inv = 1.0f / zs;
        s.x *= inv; s.y *= inv; s.z *= inv; s.w *= inv;
        ((float4*)g_w)[b * 4 + tid] = s;
    }
}

// ------------------------------------------------------------------
// 5) x[i] = dot(w[h], Wv[i]) + bv[i].  grid 512 x 256 (r14 verbatim).
// ------------------------------------------------------------------
__global__ void k_xproj(const float* __restrict__ Wv,
                        const float* __restrict__ bv) {
    __shared__ __align__(16) float ws[DM];
    __shared__ float part[8];
    const int tid = threadIdx.x;
    const int b = blockIdx.x;
    const int h = b >> 5;
    ((float4*)ws)[tid] = ((const float4*)(g_w + h * DM))[tid];
    __syncthreads();
    const int w = tid >> 5, lane = tid & 31;
    const int row = b * 2 + (w >> 2);
    const int kq = w & 3;
    const float4* wr = (const float4*)(Wv + (size_t)row * DM) + kq * 64;
    const float4* q4 = (const float4*)ws + kq * 64;
    float acc = 0.f;
#pragma unroll
    for (int k = lane; k < 64; k += 32) {
        float4 a = wr[k], bb = q4[k];
        acc += a.x * bb.x + a.y * bb.y + a.z * bb.z + a.w * bb.w;
    }
    acc = warp_red(acc);
    if (lane == 0) part[w] = acc;
    __syncthreads();
    if (tid < 2) {
        const int r = b * 2 + tid;
        const float s = part[tid * 4] + part[tid * 4 + 1]
                      + part[tid * 4 + 2] + part[tid * 4 + 3];
        g_x[r] = s + bv[r];
    }
}

// ------------------------------------------------------------------
// 6) out[i] = dot(x, Wo[i]) + bo[i].  grid 512 x 256 (r14 verbatim).
// ------------------------------------------------------------------
__global__ void k_out(const float* __restrict__ Wo,
                      const float* __restrict__ bo,
                      float* __restrict__ out) {
    __shared__ __align__(16) float xs[DM];
    __shared__ float part[8];
    const int tid = threadIdx.x;
    const int b = blockIdx.x;
    ((float4*)xs)[tid] = ((const float4*)g_x)[tid];
    __syncthreads();
    const int w = tid >> 5, lane = tid & 31;
    const int row = b * 2 + (w >> 2);
    const int kq = w & 3;
    const float4* wr = (const float4*)(Wo + (size_t)row * DM) + kq * 64;
    const float4* q4 = (const float4*)xs + kq * 64;
    float acc = 0.f;
#pragma unroll
    for (int k = lane; k < 64; k += 32) {
        float4 a = wr[k], bb = q4[k];
        acc += a.x * bb.x + a.y * bb.y + a.z * bb.z + a.w * bb.w;
    }
    acc = warp_red(acc);
    if (lane == 0) part[w] = acc;
    __syncthreads();
    if (tid < 2) {
        const int r = b * 2 + tid;
        const float s = part[tid * 4] + part[tid * 4 + 1]
                      + part[tid * 4 + 2] + part[tid * 4 + 3];
        out[r] = s + bo[r];
    }
}

// ------------------------------------------------------------------
extern "C" void kernel_launch(void* const* d_in, const int* in_sizes, int n_in,
                              void* d_out, int out_size) {
    (void)in_sizes; (void)n_in; (void)out_size;
    const float* query = (const float*)d_in[0];
    const float* key   = (const float*)d_in[1];
    const float* value = (const float*)d_in[2];
    const float* Wq    = (const float*)d_in[3];
    const float* bq    = (const float*)d_in[4];
    const float* Wk    = (const float*)d_in[5];
    const float* bk    = (const float*)d_in[6];
    const float* Wv    = (const float*)d_in[7];
    const float* bv    = (const float*)d_in[8];
    const float* Wo    = (const float*)d_in[9];
    const float* bo    = (const float*)d_in[10];
    float* out = (float*)d_out;

    cudaFuncSetAttribute(k_attn, cudaFuncAttributeMaxDynamicSharedMemorySize,
                         SM_BYTES);

    k_qproj  <<<128, 256>>>(query, Wq, bq);           // idx 0
    k_aprep  <<<128, 128>>>(Wk, bk);                  // idx 1
    k_attn   <<<NCHUNK, 256, SM_BYTES>>>(key, value); // idx 2
    k_wreduce<<<1024, 256>>>();                       // idx 3  <- ncu window
    k_xproj  <<<512, 256>>>(Wv, bv);                  // idx 4
    k_out    <<<512, 256>>>(Wo, bo, out);             // idx 5
}